// round 9
// baseline (speedup 1.0000x reference)
#include <cuda_runtime.h>
#include <cstdint>

// Problem constants
#define SDIM   64
#define CIN    16
#define COUTC  16
#define BATCH  4

// Tiling: 16 couts per block; thread tile = 8 couts x 4 x; 2 cout-groups.
#define TY         4
#define TXT       16
#define XPT        4
#define CPT        8
#define NTHREADS 128

// Windowed input tile: 16 windows of 6 floats per row (conflict-free: 3*tx mod 16)
#define WIN_W      6
#define NWIN      16
#define IN_ROW     (NWIN * WIN_W)     // 96
#define IN_H       (TY + 2)           // 6
#define IN_D       3
#define TILE_ELEMS (IN_D * IN_H * IN_ROW)   // 1728
#define IN_SLOTS   ((TILE_ELEMS + NTHREADS - 1) / NTHREADS)  // 14

// Transposed weights in global scratch: [(cin*3+kd)*3+kh][kw*16 + cout]
#define WT_ELEMS (CIN * 9 * 48)   // 6912

__device__ __align__(16) float g_wt[WT_ELEMS];

#define PACKF2(d, lo, hi) \
    asm("mov.b64 %0, {%1, %2};" : "=l"(d) : "f"(lo), "f"(hi))
#define FMAF2(d, a, b, c) \
    asm("fma.rn.f32x2 %0, %1, %2, %3;" : "=l"(d) : "l"(a), "l"(b), "l"(c))
#define UNPACKF2(lo, hi, s) \
    asm("mov.b64 {%0, %1}, %2;" : "=f"(lo), "=f"(hi) : "l"(s))

__device__ __forceinline__ uint32_t smem_u32(const void* p) {
    return (uint32_t)__cvta_generic_to_shared(p);
}

// ---- Pre-kernel: transpose weights into broadcast-friendly layout ----
__global__ void transpose_w_kernel(const float* __restrict__ Wg)
{
    int g = blockIdx.x * blockDim.x + threadIdx.x;
    if (g < COUTC * CIN * 27) {
        int cout = g / (CIN * 27);
        int rem  = g % (CIN * 27);
        int cin  = rem / 27;
        int k    = rem % 27;
        g_wt[(cin * 9 + k / 3) * 48 + (k % 3) * 16 + cout] = Wg[g];
    }
}

__global__ void __launch_bounds__(NTHREADS, 6)
conv3d_kernel(const float* __restrict__ X,
              const float* __restrict__ Bias,
              float* __restrict__ Out)
{
    __shared__ __align__(16) float s_in[2][TILE_ELEMS];      // 13.8 KB
    __shared__ int   s_soff[IN_SLOTS * NTHREADS];            // 7 KB
    __shared__ float s_bias[COUTC];

    const int tid = threadIdx.x;
    const int tx  = tid & (TXT - 1);        // 0..15  (x block of 4)
    const int ty  = (tid >> 4) & (TY - 1);  // 0..3
    const int cg  = tid >> 6;               // 0..1   (8-cout group; warp-uniform)

    const int z  = blockIdx.x;
    const int y0 = blockIdx.y * TY;
    const int b  = blockIdx.z;

    // ---- Precompute input tile-slot source offsets -> shared (cin-invariant) ----
    for (int k = 0; k < IN_SLOTS; ++k) {
        int s = tid + k * NTHREADS;
        int off = -1;
        if (s < TILE_ELEMS) {
            int r  = s / IN_ROW;
            int p  = s % IN_ROW;
            int w  = p / WIN_W;
            int o  = p % WIN_W;
            int gx = 4 * w + o - 1;
            int gz = z  + r / IN_H - 1;
            int gy = y0 + r % IN_H - 1;
            if ((unsigned)gz < SDIM && (unsigned)gy < SDIM && (unsigned)gx < SDIM)
                off = (gz * SDIM + gy) * SDIM + gx;
            else {
                s_in[0][s] = 0.0f;    // zero halo once in both buffers
                s_in[1][s] = 0.0f;
            }
        }
        s_soff[k * NTHREADS + tid] = off;
    }
    if (tid < COUTC) s_bias[tid] = Bias[tid];
    __syncthreads();   // halo zeros + s_soff visible

    const float* Xb = X + (size_t)b * CIN * (SDIM * SDIM * SDIM);

    // ---- Prologue: async-load input tile for cin=0 ----
    {
#pragma unroll
        for (int k = 0; k < IN_SLOTS; ++k) {
            int off = s_soff[k * NTHREADS + tid];
            if (off >= 0) {
                uint32_t dst = smem_u32(&s_in[0][tid + k * NTHREADS]);
                asm volatile("cp.async.ca.shared.global [%0], [%1], 4;"
                             :: "r"(dst), "l"(Xb + off));
            }
        }
        asm volatile("cp.async.commit_group;");
    }

    // Accumulators: accd[cp][j] = (out[cg*8+2cp], out[cg*8+2cp+1]) at x = 4*tx + j
    unsigned long long accd[4][XPT];
#pragma unroll
    for (int cp = 0; cp < 4; ++cp)
#pragma unroll
        for (int j = 0; j < XPT; ++j) accd[cp][j] = 0ull;

#pragma unroll 1
    for (int cin = 0; cin < CIN; ++cin) {
        asm volatile("cp.async.wait_group 0;");
        __syncthreads();

        // issue next cin's input into the other buffer
        if (cin + 1 < CIN) {
            const float* Xc = Xb + (size_t)(cin + 1) * (SDIM * SDIM * SDIM);
            float* ibuf = s_in[(cin + 1) & 1];
#pragma unroll
            for (int k = 0; k < IN_SLOTS; ++k) {
                int off = s_soff[k * NTHREADS + tid];
                if (off >= 0) {
                    uint32_t dst = smem_u32(&ibuf[tid + k * NTHREADS]);
                    asm volatile("cp.async.ca.shared.global [%0], [%1], 4;"
                                 :: "r"(dst), "l"(Xc + off));
                }
            }
            asm volatile("cp.async.commit_group;");
        }

        // ---- Compute: conflict-free 6-float window LDS + broadcast weight LDG ----
        const float* cur = s_in[cin & 1];
        const float* wci = g_wt + cin * (9 * 48) + cg * CPT;
#pragma unroll
        for (int kd = 0; kd < 3; ++kd) {
#pragma unroll
            for (int kh = 0; kh < 3; ++kh) {
                // weights: 8 couts per kw = 2 LDG.128 broadcasts -> 4 u64 pairs
                const float* wp = wci + (kd * 3 + kh) * 48;
                unsigned long long wv[3][4];
#pragma unroll
                for (int kw = 0; kw < 3; ++kw) {
                    ulonglong2 q0 = __ldg(reinterpret_cast<const ulonglong2*>(wp + kw * 16));
                    ulonglong2 q1 = __ldg(reinterpret_cast<const ulonglong2*>(wp + kw * 16 + 4));
                    wv[kw][0] = q0.x; wv[kw][1] = q0.y;
                    wv[kw][2] = q1.x; wv[kw][3] = q1.y;
                }

                // inputs: 6 floats via 3 aligned LDS.64, duplicated per lane
                const float* rowp = cur + (kd * IN_H + ty + kh) * IN_ROW + tx * WIN_W;
                const float2* r2 = reinterpret_cast<const float2*>(rowp);
                unsigned long long dup[WIN_W];
#pragma unroll
                for (int i = 0; i < 3; ++i) {
                    float2 p = r2[i];
                    PACKF2(dup[2 * i],     p.x, p.x);
                    PACKF2(dup[2 * i + 1], p.y, p.y);
                }

#pragma unroll
                for (int kw = 0; kw < 3; ++kw)
#pragma unroll
                    for (int cp = 0; cp < 4; ++cp)
#pragma unroll
                        for (int j = 0; j < XPT; ++j)
                            FMAF2(accd[cp][j], dup[j + kw], wv[kw][cp], accd[cp][j]);
            }
        }
    }

    // ---- Epilogue: unpack, bias, vectorized stores ----
    const int x0 = tx * XPT;
    const int y  = y0 + ty;
#pragma unroll
    for (int cp = 0; cp < 4; ++cp) {
        float o0[XPT], o1[XPT];
#pragma unroll
        for (int j = 0; j < XPT; ++j) UNPACKF2(o0[j], o1[j], accd[cp][j]);

        const int c0 = cg * CPT + 2 * cp;
        const float b0 = s_bias[c0];
        const float b1 = s_bias[c0 + 1];

        float* op0 = Out + ((((size_t)b * COUTC + c0)     * SDIM + z) * SDIM + y) * SDIM + x0;
        float* op1 = Out + ((((size_t)b * COUTC + c0 + 1) * SDIM + z) * SDIM + y) * SDIM + x0;

        reinterpret_cast<float4*>(op0)[0] = make_float4(o0[0] + b0, o0[1] + b0, o0[2] + b0, o0[3] + b0);
        reinterpret_cast<float4*>(op1)[0] = make_float4(o1[0] + b1, o1[1] + b1, o1[2] + b1, o1[3] + b1);
    }
}

extern "C" void kernel_launch(void* const* d_in, const int* in_sizes, int n_in,
                              void* d_out, int out_size)
{
    const float* x    = (const float*)d_in[0];
    const float* w    = (const float*)d_in[1];
    const float* bias = (const float*)d_in[2];
    float* out        = (float*)d_out;

    transpose_w_kernel<<<(COUTC * CIN * 27 + NTHREADS - 1) / NTHREADS, NTHREADS>>>(w);

    dim3 grid(SDIM, SDIM / TY, BATCH);
    conv3d_kernel<<<grid, NTHREADS>>>(x, bias, out);
}